// round 13
// baseline (speedup 1.0000x reference)
#include <cuda_runtime.h>

// AudioDeviceModel_89008902242543  — R12
//
// s[b]      = dot(x[b,:], w1[0,:,0]) + b1+b2+b3+b4+b5
// out[b,d]  = s[b]*wd[d] + bd[d]            (B=8192, L=16384, D=128)
//
// HBM-read-bound (512 MB of x). R11 proved split-K helps the dot kernel
// (~73-74us) but its separate epilogue kernel cost 7.2us. R12 fuses the
// epilogue via the CUB tile-status pattern: each split CTA publishes its
// partial (fence + atomicAdd on a per-pair counter); the SECOND finisher
// sums both partials in fixed order (deterministic), applies wd/bd, and
// resets the counter (graph-replay safe). One launch; epilogue overlaps
// the ramp-down tail for free.

#define B_ROWS  8192
#define L_COLS  16384
#define L4      (L_COLS / 4)    // 4096 float4 per row
#define RPB     2               // rows per CTA
#define SPLIT   2               // column splits per row-pair
#define L4S     (L4 / SPLIT)    // 2048 float4 per split
#define NPAIRS  (B_ROWS / RPB)  // 4096
#define NT      256
#define NWARPS  (NT / 32)
#define UNR     4               // column steps per batch
#define ITERS   (L4S / NT)      // 8 -> 2 batches of UNR

__device__ float g_partial[B_ROWS * SPLIT];
__device__ int   g_count[NPAIRS];     // zero-init; reset after use each launch

__device__ __forceinline__ float dot4_acc(float4 xx, float4 w, float a) {
    return fmaf(xx.x, w.x, fmaf(xx.y, w.y, fmaf(xx.z, w.z, fmaf(xx.w, w.w, a))));
}

__global__ __launch_bounds__(NT, 4)
void audio_model_kernel(const float* __restrict__ x,
                        const float* __restrict__ w1,
                        const float* __restrict__ b1,
                        const float* __restrict__ b2,
                        const float* __restrict__ b3,
                        const float* __restrict__ b4,
                        const float* __restrict__ b5,
                        const float* __restrict__ wd,
                        const float* __restrict__ bd,
                        float* __restrict__ out)
{
    const int pair  = blockIdx.x >> 1;       // row-pair index
    const int split = blockIdx.x & 1;        // column half
    const int b0    = pair * RPB;
    const int tid   = threadIdx.x;

    const float4* __restrict__ wv = reinterpret_cast<const float4*>(w1);
    const float4* __restrict__ xv =
        reinterpret_cast<const float4*>(x) + (size_t)b0 * L4;

    float acc[RPB];
#pragma unroll
    for (int r = 0; r < RPB; r++) acc[r] = 0.0f;

    int i = split * L4S + tid;
#pragma unroll 1
    for (int it = 0; it < ITERS; it += UNR, i += UNR * NT) {
        // Front-batch the 8 HBM loads (2 rows x 4 column steps).
        float4 xx[RPB][UNR];
#pragma unroll
        for (int u = 0; u < UNR; u++)
#pragma unroll
            for (int r = 0; r < RPB; r++)
                xx[r][u] = __ldcs(&xv[(size_t)r * L4 + i + u * NT]);

        // w loads are L2 hits; JIT to save registers.
#pragma unroll
        for (int u = 0; u < UNR; u++) {
            float4 w = wv[i + u * NT];
#pragma unroll
            for (int r = 0; r < RPB; r++)
                acc[r] = dot4_acc(xx[r][u], w, acc[r]);
        }
    }

    // Intra-warp tree reduction for each row accumulator.
#pragma unroll
    for (int r = 0; r < RPB; r++) {
#pragma unroll
        for (int off = 16; off > 0; off >>= 1)
            acc[r] += __shfl_xor_sync(0xffffffffu, acc[r], off);
    }

    __shared__ float part[NWARPS][RPB];
    __shared__ int s_old;

    const int wid = tid >> 5;
    const int lid = tid & 31;
    if (lid == 0) {
#pragma unroll
        for (int r = 0; r < RPB; r++) part[wid][r] = acc[r];
    }
    __syncthreads();

    if (tid < RPB) {
        float s = 0.0f;
#pragma unroll
        for (int w = 0; w < NWARPS; w++) s += part[w][tid];
        g_partial[(b0 + tid) * SPLIT + split] = s;   // deterministic slot
    }
    __syncthreads();   // partial writes happen-before tid0's fence

    if (tid == 0) {
        __threadfence();                              // release partials
        s_old = atomicAdd(&g_count[pair], 1);
    }
    __syncthreads();

    if (s_old == 1) {
        // Second finisher: both partials are published. Acquire + epilogue.
        __threadfence();
        // 256 threads -> 2 rows x 128 outputs. Fixed summation order
        // (split0 + split1) keeps the result bit-deterministic.
        const int r = tid >> 7;
        const int d = tid & 127;
        const float bias = b1[0] + b2[0] + b3[0] + b4[0] + b5[0];
        const float s = g_partial[(b0 + r) * SPLIT + 0]
                      + g_partial[(b0 + r) * SPLIT + 1] + bias;
        out[(size_t)(b0 + r) * 128 + d] = fmaf(s, wd[d], bd[d]);

        if (tid == 0) g_count[pair] = 0;   // reset for next graph replay
    }
}

extern "C" void kernel_launch(void* const* d_in, const int* in_sizes, int n_in,
                              void* d_out, int out_size)
{
    // metadata order: x, w1, b1, w2, b2, w3, b3, w4, b4, w5, b5, wd, bd
    const float* x  = (const float*)d_in[0];
    const float* w1 = (const float*)d_in[1];
    const float* b1 = (const float*)d_in[2];
    const float* b2 = (const float*)d_in[4];
    const float* b3 = (const float*)d_in[6];
    const float* b4 = (const float*)d_in[8];
    const float* b5 = (const float*)d_in[10];
    const float* wd = (const float*)d_in[11];
    const float* bd = (const float*)d_in[12];
    float* out = (float*)d_out;

    dim3 grid(NPAIRS * SPLIT);   // 8192 CTAs (half row-pairs)
    audio_model_kernel<<<grid, NT>>>(x, w1, b1, b2, b3, b4, b5, wd, bd, out);
}

// round 14
// speedup vs baseline: 1.0308x; 1.0308x over previous
#include <cuda_runtime.h>

// AudioDeviceModel_89008902242543  — R13
//
// s[b]      = dot(x[b,:], w1[0,:,0]) + b1+b2+b3+b4+b5
// out[b,d]  = s[b]*wd[d] + bd[d]            (B=8192, L=16384, D=128)
//
// HBM-read-bound (512 MB of x). R12's fused finisher regressed: its
// __threadfence -> CCTL.IVALL flushed sibling CTAs' L1 mid-stream.
// R13 = R11's proven split-K dot kernel (grid 8192, half row-pairs,
// no fences/atomics) + a ONE-WAVE epilogue: 1024 CTAs x 256 thr, one
// float4 output per thread (R11's version was 4096 tiny CTAs = 28
// latency-bound waves = 7.2us; this is ~2us).

#define B_ROWS  8192
#define L_COLS  16384
#define L4      (L_COLS / 4)    // 4096 float4 per row
#define RPB     2               // rows per CTA
#define SPLIT   2               // column splits per row-pair
#define L4S     (L4 / SPLIT)    // 2048 float4 per split
#define NT      256
#define NWARPS  (NT / 32)
#define UNR     4               // column steps per batch
#define ITERS   (L4S / NT)      // 8 -> 2 batches of UNR

__device__ float g_partial[B_ROWS * SPLIT];

__device__ __forceinline__ float dot4_acc(float4 xx, float4 w, float a) {
    return fmaf(xx.x, w.x, fmaf(xx.y, w.y, fmaf(xx.z, w.z, fmaf(xx.w, w.w, a))));
}

__global__ __launch_bounds__(NT, 4)
void audio_dot_kernel(const float* __restrict__ x,
                      const float* __restrict__ w1)
{
    const int pair  = blockIdx.x >> 1;       // row-pair index
    const int split = blockIdx.x & 1;        // column half
    const int b0    = pair * RPB;
    const int tid   = threadIdx.x;

    const float4* __restrict__ wv = reinterpret_cast<const float4*>(w1);
    const float4* __restrict__ xv =
        reinterpret_cast<const float4*>(x) + (size_t)b0 * L4;

    float acc[RPB];
#pragma unroll
    for (int r = 0; r < RPB; r++) acc[r] = 0.0f;

    int i = split * L4S + tid;
#pragma unroll 1
    for (int it = 0; it < ITERS; it += UNR, i += UNR * NT) {
        // Front-batch the 8 HBM loads (2 rows x 4 column steps).
        float4 xx[RPB][UNR];
#pragma unroll
        for (int u = 0; u < UNR; u++)
#pragma unroll
            for (int r = 0; r < RPB; r++)
                xx[r][u] = __ldcs(&xv[(size_t)r * L4 + i + u * NT]);

        // w loads are L2 hits; JIT to save registers.
#pragma unroll
        for (int u = 0; u < UNR; u++) {
            float4 w = wv[i + u * NT];
#pragma unroll
            for (int r = 0; r < RPB; r++)
                acc[r] = dot4_acc(xx[r][u], w, acc[r]);
        }
    }

    // Intra-warp tree reduction for each row accumulator.
#pragma unroll
    for (int r = 0; r < RPB; r++) {
#pragma unroll
        for (int off = 16; off > 0; off >>= 1)
            acc[r] += __shfl_xor_sync(0xffffffffu, acc[r], off);
    }

    __shared__ float part[NWARPS][RPB];
    const int wid = tid >> 5;
    const int lid = tid & 31;
    if (lid == 0) {
#pragma unroll
        for (int r = 0; r < RPB; r++) part[wid][r] = acc[r];
    }
    __syncthreads();

    if (tid < RPB) {
        float s = 0.0f;
#pragma unroll
        for (int w = 0; w < NWARPS; w++) s += part[w][tid];
        g_partial[(b0 + tid) * SPLIT + split] = s;   // deterministic slot
    }
}

__global__ __launch_bounds__(NT)
void audio_epilogue_kernel(const float* __restrict__ b1,
                           const float* __restrict__ b2,
                           const float* __restrict__ b3,
                           const float* __restrict__ b4,
                           const float* __restrict__ b5,
                           const float* __restrict__ wd,
                           const float* __restrict__ bd,
                           float* __restrict__ out)
{
    // One float4 (4 output cols) per thread: 8192 rows x 32 float4 = 262144
    // threads = 1024 CTAs x 256. Single wave, fully coalesced STG.128.
    const int gid = blockIdx.x * NT + threadIdx.x;
    const int row = gid >> 5;        // 32 float4 per row
    const int c4  = gid & 31;

    const float bias = b1[0] + b2[0] + b3[0] + b4[0] + b5[0];
    // Fixed order (split0 + split1) -> bit-deterministic.
    const float s = g_partial[row * SPLIT + 0]
                  + g_partial[row * SPLIT + 1] + bias;

    const float4 w = reinterpret_cast<const float4*>(wd)[c4];
    const float4 b = reinterpret_cast<const float4*>(bd)[c4];
    float4 o;
    o.x = fmaf(s, w.x, b.x);
    o.y = fmaf(s, w.y, b.y);
    o.z = fmaf(s, w.z, b.z);
    o.w = fmaf(s, w.w, b.w);
    reinterpret_cast<float4*>(out)[gid] = o;
}

extern "C" void kernel_launch(void* const* d_in, const int* in_sizes, int n_in,
                              void* d_out, int out_size)
{
    // metadata order: x, w1, b1, w2, b2, w3, b3, w4, b4, w5, b5, wd, bd
    const float* x  = (const float*)d_in[0];
    const float* w1 = (const float*)d_in[1];
    const float* b1 = (const float*)d_in[2];
    const float* b2 = (const float*)d_in[4];
    const float* b3 = (const float*)d_in[6];
    const float* b4 = (const float*)d_in[8];
    const float* b5 = (const float*)d_in[10];
    const float* wd = (const float*)d_in[11];
    const float* bd = (const float*)d_in[12];
    float* out = (float*)d_out;

    dim3 gridA((B_ROWS / RPB) * SPLIT);           // 8192 CTAs
    audio_dot_kernel<<<gridA, NT>>>(x, w1);

    dim3 gridB((B_ROWS * 128 / 4) / NT);          // 1024 CTAs
    audio_epilogue_kernel<<<gridB, NT>>>(b1, b2, b3, b4, b5, wd, bd, out);
}